// round 4
// baseline (speedup 1.0000x reference)
#include <cuda_runtime.h>
#include <cuda_bf16.h>

#define NJ 24
#define EPSF 1e-6f

typedef unsigned long long ull;

// ---- packed f32x2 helpers ----
__device__ __forceinline__ ull f2_fma(ull a, ull b, ull c) {
    ull d; asm("fma.rn.f32x2 %0, %1, %2, %3;" : "=l"(d) : "l"(a), "l"(b), "l"(c)); return d;
}
__device__ __forceinline__ ull f2_mul(ull a, ull b) {
    ull d; asm("mul.rn.f32x2 %0, %1, %2;" : "=l"(d) : "l"(a), "l"(b)); return d;
}
__device__ __forceinline__ ull f2_add(ull a, ull b) {
    ull d; asm("add.rn.f32x2 %0, %1, %2;" : "=l"(d) : "l"(a), "l"(b)); return d;
}
__device__ __forceinline__ ull f2_pack(float lo, float hi) {
    ull d;
    asm("mov.b64 %0, {%1, %2};" : "=l"(d) : "r"(__float_as_uint(lo)), "r"(__float_as_uint(hi)));
    return d;
}
__device__ __forceinline__ void f2_unpack(ull a, float& lo, float& hi) {
    unsigned int l, h;
    asm("mov.b64 {%0, %1}, %2;" : "=r"(l), "=r"(h) : "l"(a));
    lo = __uint_as_float(l); hi = __uint_as_float(h);
}
__device__ __forceinline__ float sqrt_ap(float x) {
    float r; asm("sqrt.approx.f32 %0, %1;" : "=f"(r) : "f"(x)); return r;
}
__device__ __forceinline__ float rcp_ap(float x) {
    float r; asm("rcp.approx.f32 %0, %1;" : "=f"(r) : "f"(x)); return r;
}

// Shared layout per joint: 24 duplicated {c,c} 64-bit pairs.
//  0..11 : transform rows 0..2 (m00..m23)
// 12..14 : loc (lx,ly,lz)
// 15     : a0' = C0*f0 + 0.5 - C2c*f6     (const term, a6*n2 folded out)
// 16..18 : a1=-C1*f1, a2=C1*f2, a3=-C1*f3 (linear, applied to d)
// 19..23 : a4=B*f4, a5=-B*f5, b6=3*C2c*f6, a7=-B*f7, a8=D*f8 (quadratic on d)

__global__ __launch_bounds__(256)
void shCaster_kernel(const float* __restrict__ xyz,
                     const float* __restrict__ vdir,
                     const float* __restrict__ transforms,
                     const float* __restrict__ sh_feats,
                     const float* __restrict__ locs,
                     float* __restrict__ out,
                     int half, int n)
{
    __shared__ __align__(16) ull S2[NJ * 24];

    {
        const float coef0 = 0.28209479177387814f;
        const float coefA = 0.4886025119029199f;
        const float coefB = 1.0925484305920792f;
        const float coefC = 0.31539156525252005f;
        const float coefD = 0.5462742152960396f;
        for (int idx = threadIdx.x; idx < NJ * 24; idx += blockDim.x) {
            int j = idx / 24, k = idx % 24;
            float v;
            if (k < 12) {
                v = transforms[j * 16 + k];
            } else if (k < 15) {
                v = locs[j * 3 + (k - 12)];
            } else if (k == 15) {
                v = coef0 * sh_feats[j * 9 + 0] + 0.5f - coefC * sh_feats[j * 9 + 6];
            } else if (k == 16) {
                v = -coefA * sh_feats[j * 9 + 1];
            } else if (k == 17) {
                v =  coefA * sh_feats[j * 9 + 2];
            } else if (k == 18) {
                v = -coefA * sh_feats[j * 9 + 3];
            } else if (k == 19) {
                v =  coefB * sh_feats[j * 9 + 4];
            } else if (k == 20) {
                v = -coefB * sh_feats[j * 9 + 5];
            } else if (k == 21) {
                v = 3.0f * coefC * sh_feats[j * 9 + 6];
            } else if (k == 22) {
                v = -coefB * sh_feats[j * 9 + 7];
            } else {
                v =  coefD * sh_feats[j * 9 + 8];
            }
            unsigned int b = __float_as_uint(v);
            S2[j * 24 + k] = ((ull)b << 32) | b;
        }
    }
    __syncthreads();

    int t = blockIdx.x * blockDim.x + threadIdx.x;
    if (t >= half) return;
    int i0 = t, i1 = t + half;

    const ull x2 = f2_pack(__ldg(&xyz[3 * i0]),     __ldg(&xyz[3 * i1]));
    const ull y2 = f2_pack(__ldg(&xyz[3 * i0 + 1]), __ldg(&xyz[3 * i1 + 1]));
    const ull z2 = f2_pack(__ldg(&xyz[3 * i0 + 2]), __ldg(&xyz[3 * i1 + 2]));

    const ull NEG1 = f2_pack(-1.f, -1.f);

    ull wsum2 = 0ull;
    ull ox2 = 0ull, oy2 = 0ull, oz2 = 0ull;
    // rotation-matrix accumulator: Sum w * R_j (3x3)
    ull t00 = 0ull, t01 = 0ull, t02 = 0ull;
    ull t10 = 0ull, t11 = 0ull, t12 = 0ull;
    ull t20 = 0ull, t21 = 0ull, t22 = 0ull;

#pragma unroll
    for (int j = 0; j < NJ; ++j) {
        const ulonglong2* C = reinterpret_cast<const ulonglong2*>(S2 + j * 24);
        const ulonglong2 c0 = C[0];   // m00 m01
        const ulonglong2 c1 = C[1];   // m02 m03
        const ulonglong2 c2 = C[2];   // m10 m11
        const ulonglong2 c3 = C[3];   // m12 m13
        const ulonglong2 c4 = C[4];   // m20 m21
        const ulonglong2 c5 = C[5];   // m22 m23
        const ulonglong2 c6 = C[6];   // lx  ly
        const ulonglong2 c7 = C[7];   // lz  a0'
        const ulonglong2 c8 = C[8];   // a1  a2
        const ulonglong2 c9 = C[9];   // a3  a4
        const ulonglong2 cA = C[10];  // a5  b6
        const ulonglong2 cB = C[11];  // a7  a8

        // p = (M [x,1])[:3]
        ull px = f2_fma(c0.x, x2, f2_fma(c0.y, y2, f2_fma(c1.x, z2, c1.y)));
        ull py = f2_fma(c2.x, x2, f2_fma(c2.y, y2, f2_fma(c3.x, z2, c3.y)));
        ull pz = f2_fma(c4.x, x2, f2_fma(c4.y, y2, f2_fma(c5.x, z2, c5.y)));

        // d = loc - p
        ull dx = f2_fma(px, NEG1, c6.x);
        ull dy = f2_fma(py, NEG1, c6.y);
        ull dz = f2_fma(pz, NEG1, c7.x);

        ull sx = f2_mul(dx, dx);
        ull sy = f2_mul(dy, dy);
        ull sz = f2_mul(dz, dz);
        ull n2 = f2_add(f2_add(sx, sy), sz);

        // linear SH part on d
        ull L = f2_fma(c8.x, dy, f2_fma(c8.y, dz, f2_mul(c9.x, dx)));

        // quadratic SH part on d
        ull xy = f2_mul(dx, dy);
        ull yz = f2_mul(dy, dz);
        ull xz = f2_mul(dx, dz);
        ull t2d = f2_fma(sy, NEG1, sx);          // dx^2 - dy^2
        ull Q = f2_mul(c9.y, xy);
        Q = f2_fma(cA.x, yz, Q);
        Q = f2_fma(cA.y, sz, Q);                 // b6 * dz^2
        Q = f2_fma(cB.x, xz, Q);
        Q = f2_fma(cB.y, t2d, Q);

        // s = sqrt(n2) per lane
        float n2a, n2b; f2_unpack(n2, n2a, n2b);
        ull s2 = f2_pack(sqrt_ap(n2a), sqrt_ap(n2b));

        // denom = rad * n2 = a0'*n2 + L*s + Q ;  numer = len * n2 = n2 * s
        ull denom = f2_fma(c7.y, n2, Q);
        denom = f2_fma(L, s2, denom);
        ull numer = f2_mul(n2, s2);
        ull tt = f2_fma(numer, NEG1, denom);     // denom - numer

        // w = relu(denom-numer) / denom   (==0 whenever rad<EPS or rad<=0)
        float ta, tb; f2_unpack(tt, ta, tb);
        float da, db; f2_unpack(denom, da, db);
        float wa = fmaxf(ta, 0.f) * rcp_ap(fmaxf(da, 1e-30f));
        float wb = fmaxf(tb, 0.f) * rcp_ap(fmaxf(db, 1e-30f));
        ull w2 = f2_pack(wa, wb);

        wsum2 = f2_add(wsum2, w2);
        ox2 = f2_fma(w2, px, ox2);
        oy2 = f2_fma(w2, py, oy2);
        oz2 = f2_fma(w2, pz, oz2);

        t00 = f2_fma(w2, c0.x, t00);
        t01 = f2_fma(w2, c0.y, t01);
        t02 = f2_fma(w2, c1.x, t02);
        t10 = f2_fma(w2, c2.x, t10);
        t11 = f2_fma(w2, c2.y, t11);
        t12 = f2_fma(w2, c3.x, t12);
        t20 = f2_fma(w2, c4.x, t20);
        t21 = f2_fma(w2, c4.y, t21);
        t22 = f2_fma(w2, c5.x, t22);
    }

    // ---- epilogue ----
    const float vxa = __ldg(&vdir[3 * i0]),     vxb = __ldg(&vdir[3 * i1]);
    const float vya = __ldg(&vdir[3 * i0 + 1]), vyb = __ldg(&vdir[3 * i1 + 1]);
    const float vza = __ldg(&vdir[3 * i0 + 2]), vzb = __ldg(&vdir[3 * i1 + 2]);

    float wsa, wsb;  f2_unpack(wsum2, wsa, wsb);
    float oxa, oxb;  f2_unpack(ox2, oxa, oxb);
    float oya, oyb;  f2_unpack(oy2, oya, oyb);
    float oza, ozb;  f2_unpack(oz2, oza, ozb);
    float a00, b00;  f2_unpack(t00, a00, b00);
    float a01, b01;  f2_unpack(t01, a01, b01);
    float a02, b02;  f2_unpack(t02, a02, b02);
    float a10, b10;  f2_unpack(t10, a10, b10);
    float a11, b11;  f2_unpack(t11, a11, b11);
    float a12, b12;  f2_unpack(t12, a12, b12);
    float a20, b20;  f2_unpack(t20, a20, b20);
    float a21, b21;  f2_unpack(t21, a21, b21);
    float a22, b22;  f2_unpack(t22, a22, b22);

    float xa, xb, ya, yb, za, zb;
    f2_unpack(x2, xa, xb); f2_unpack(y2, ya, yb); f2_unpack(z2, za, zb);

    float* outv = out + (size_t)3 * n;

    if (wsa > EPSF) {
        float inv = rcp_ap(wsa);
        out[3 * i0]     = oxa * inv;
        out[3 * i0 + 1] = oya * inv;
        out[3 * i0 + 2] = oza * inv;
        outv[3 * i0]     = fmaf(a00, vxa, fmaf(a01, vya, a02 * vza)) * inv;
        outv[3 * i0 + 1] = fmaf(a10, vxa, fmaf(a11, vya, a12 * vza)) * inv;
        outv[3 * i0 + 2] = fmaf(a20, vxa, fmaf(a21, vya, a22 * vza)) * inv;
    } else {
        out[3 * i0] = xa;  out[3 * i0 + 1] = ya;  out[3 * i0 + 2] = za;
        outv[3 * i0] = vxa; outv[3 * i0 + 1] = vya; outv[3 * i0 + 2] = vza;
    }
    if (wsb > EPSF) {
        float inv = rcp_ap(wsb);
        out[3 * i1]     = oxb * inv;
        out[3 * i1 + 1] = oyb * inv;
        out[3 * i1 + 2] = ozb * inv;
        outv[3 * i1]     = fmaf(b00, vxb, fmaf(b01, vyb, b02 * vzb)) * inv;
        outv[3 * i1 + 1] = fmaf(b10, vxb, fmaf(b11, vyb, b12 * vzb)) * inv;
        outv[3 * i1 + 2] = fmaf(b20, vxb, fmaf(b21, vyb, b22 * vzb)) * inv;
    } else {
        out[3 * i1] = xb;  out[3 * i1 + 1] = yb;  out[3 * i1 + 2] = zb;
        outv[3 * i1] = vxb; outv[3 * i1 + 1] = vyb; outv[3 * i1 + 2] = vzb;
    }
}

extern "C" void kernel_launch(void* const* d_in, const int* in_sizes, int n_in,
                              void* d_out, int out_size) {
    const float* xyz        = (const float*)d_in[0];
    const float* viewdirs   = (const float*)d_in[1];
    const float* transforms = (const float*)d_in[2];
    // d_in[3] = ray_valid — unused
    const float* sh_feats   = (const float*)d_in[4];
    const float* locs       = (const float*)d_in[5];
    float* out = (float*)d_out;

    int n = in_sizes[0] / 3;      // 524288
    int half = n / 2;             // 262144
    int threads = 256;
    int blocks = (half + threads - 1) / threads;
    shCaster_kernel<<<blocks, threads>>>(xyz, viewdirs, transforms, sh_feats,
                                         locs, out, half, n);
}